// round 13
// baseline (speedup 1.0000x reference)
#include <cuda_runtime.h>
#include <cuda_fp16.h>
#include <math.h>
#include <stdint.h>
#include <mma.h>

using namespace nvcuda;

// ---------------- problem constants ----------------
#define NR 2000
#define NP 1512
#define MROWS 3512            // NR + NP
#define DCOL 512              // e columns
#define BBATCH 8192
#define E_FLOATS (3512*512)           // 1798144
#define OUT_OFF  E_FLOATS             // output[8192,2]
#define FLAT_OFF (E_FLOATS + 8192*2)  // flat[8192,8192]

#define KATT 3000
#define KFUN 5603
#define KFUN_PAD 5632          // keeps rows 16B-aligned as halves (5632*2 % 16 == 0)

// scratch (allocation-free rule: __device__ globals) — fp16 GEMM operands
__device__ __half g_H1[(size_t)3512 * 2048];
__device__ __half g_H2[(size_t)3512 * 4096];
__device__ __half g_AA[(size_t)3512 * KATT];       // [r_att ; p_att]
__device__ __half g_AF[(size_t)3512 * KFUN_PAD];   // padded [r_fun ; p_fun]
__device__ __half g_WT1[(size_t)2048 * KATT];      // W_att1^T
__device__ __half g_WT2[(size_t)4096 * KFUN_PAD];  // W_fun1^T (padded stride)
__device__ __half g_WT3[(size_t)256 * 2048];       // W_att2^T
__device__ __half g_WT4[(size_t)256 * 4096];       // W_fun2^T

__device__ __forceinline__ float geluf(float x) {
    return 0.5f * x * (1.0f + erff(x * 0.70710678118654752440f));
}
__device__ __forceinline__ float sigmf(float x) {
    return 1.0f / (1.0f + expf(-x));
}
__device__ __forceinline__ float lrelu(float x) {
    return (x >= 0.0f) ? x : 0.01f * x;
}
__device__ __forceinline__ float tanh_fast(float x) {
    float y;
    asm("tanh.approx.f32 %0, %1;" : "=f"(y) : "f"(x));
    return y;
}

// ---- packed f32x2 helpers (B300 FFMA2 path; PTX fma.rn.f32x2, base sm_100+) ----
__device__ __forceinline__ unsigned long long pack2(float lo, float hi) {
    unsigned long long r;
    asm("mov.b64 %0, {%1, %2};" : "=l"(r) : "f"(lo), "f"(hi));
    return r;
}
__device__ __forceinline__ void fma2(unsigned long long& d,
                                     unsigned long long a, unsigned long long b) {
    asm("fma.rn.f32x2 %0, %1, %2, %0;" : "+l"(d) : "l"(a), "l"(b));
}
__device__ __forceinline__ float2 unpack2(unsigned long long v) {
    float2 f;
    asm("mov.b64 {%0, %1}, %2;" : "=f"(f.x), "=f"(f.y) : "l"(v));
    return f;
}

#define CP_ASYNC16(dst, src, sz) \
    asm volatile("cp.async.cg.shared.global [%0], [%1], 16, %2;" \
        :: "r"(dst), "l"(src), "r"(sz))
#define CP_COMMIT() asm volatile("cp.async.commit_group;" ::: "memory")
#define CP_WAIT1()  asm volatile("cp.async.wait_group 1;" ::: "memory")

__device__ __forceinline__ uint32_t smem_u32(const void* p) {
    uint32_t a;
    asm("{ .reg .u64 t; cvta.to.shared.u64 t, %1; cvt.u32.u64 %0, t; }" : "=r"(a) : "l"(p));
    return a;
}

// ---------------- padded copy float -> half ----------------
__global__ void pad_copy_h(const float* __restrict__ src, __half* __restrict__ dst,
                           int K, int ldd)
{
    int r = blockIdx.x;
    const float* s = src + (size_t)r * K;
    __half* d = dst + (size_t)r * ldd;
    for (int c = threadIdx.x; c < K; c += blockDim.x)
        d[c] = __float2half_rn(s[c]);
}

// ---------------- weight transpose float -> half: out[n*ldo+k] = in[k*N+n] ----------------
__global__ void transpose_h(const float* __restrict__ in, __half* __restrict__ out,
                            int K, int N, int ldo)
{
    __shared__ float t[32][33];
    int k0 = blockIdx.x * 32, n0 = blockIdx.y * 32;
    int x = threadIdx.x, y = threadIdx.y;   // 32 x 8
#pragma unroll
    for (int r = 0; r < 32; r += 8) {
        int k = k0 + y + r, n = n0 + x;
        t[y + r][x] = (k < K && n < N) ? in[(size_t)k * N + n] : 0.0f;
    }
    __syncthreads();
#pragma unroll
    for (int r = 0; r < 32; r += 8) {
        int n = n0 + y + r, k = k0 + x;
        if (n < N && k < K) out[(size_t)n * ldo + k] = __float2half_rn(t[x][y + r]);
    }
}

// ---------------- wmma fp16 GEMM, CTA tile 128x256x32, warp tile 64x64 ----------------
#define AS_STRIDE 40                 // halves; 80B row stride
#define TILE_A (128 * AS_STRIDE)     // 5120 halves
#define TILE_B (256 * AS_STRIDE)     // 10240 halves
#define STAGE_HALFS (TILE_A + TILE_B)            // 15360 halves = 30720 B
#define NSTAGE 3
#define GEMM_SMEM (NSTAGE * STAGE_HALFS * 2)     // 92160 B

__device__ __forceinline__ void load_tile_h(__half* stage,
                                            const char* Arow,
                                            const char* Brow0, const char* Brow1,
                                            long kb, long Kbytes, int tid)
{
    __half* As = stage;
    __half* Bs = stage + TILE_A;
    const int row = tid >> 1;            // 0..127
    const int cb0 = (tid & 1) * 32;      // byte offset within the 64B row chunk
    uint32_t dA  = smem_u32(As + row * AS_STRIDE) + cb0;
    uint32_t dB0 = smem_u32(Bs + row * AS_STRIDE) + cb0;
    uint32_t dB1 = smem_u32(Bs + (row + 128) * AS_STRIDE) + cb0;
#pragma unroll
    for (int c = 0; c < 2; ++c) {
        long off = kb + cb0 + c * 16;
        long rem = Kbytes - off;
        int sz = rem >= 16 ? 16 : (rem > 0 ? (int)rem : 0);
        CP_ASYNC16(dA + c * 16, Arow + off, sz);
        CP_ASYNC16(dB0 + c * 16, Brow0 + off, sz);
        CP_ASYNC16(dB1 + c * 16, Brow1 + off, sz);
    }
    CP_COMMIT();
}

template <int ACT>   // 0 = gelu -> half, 1 = sigmoid -> float
__global__ void __launch_bounds__(256, 1)
gemm_h(const __half* __restrict__ A, const __half* __restrict__ BT,
       const float* __restrict__ bias, void* __restrict__ Cv,
       int M, int K, int lda, int ldb, int ldc, int coff)
{
    extern __shared__ __half smemh[];

    const int tid = threadIdx.x;
    const int wid = tid >> 5;
    const int wm = (wid & 1) * 64;          // warp m offset (2 warps along m)
    const int wn = (wid >> 1) * 64;         // warp n offset (4 warps along n)
    const int m0 = blockIdx.x * 128, n0 = blockIdx.y * 256;

    int gr = m0 + (tid >> 1); if (gr >= M) gr = M - 1;
    const char* Arow  = (const char*)(A + (size_t)gr * lda);
    const char* Brow0 = (const char*)(BT + (size_t)(n0 + (tid >> 1)) * ldb);
    const char* Brow1 = (const char*)(BT + (size_t)(n0 + (tid >> 1) + 128) * ldb);
    const long Kbytes = (long)K * 2;
    const int T = (K + 31) / 32;            // 32 halves (64B) per k-block

    wmma::fragment<wmma::accumulator, 16, 16, 16, float> acc[4][4];
#pragma unroll
    for (int mt = 0; mt < 4; ++mt)
#pragma unroll
        for (int nt = 0; nt < 4; ++nt)
            wmma::fill_fragment(acc[mt][nt], 0.0f);

    // prologue: 2 tiles in flight
    load_tile_h(smemh, Arow, Brow0, Brow1, 0, Kbytes, tid);
    if (T > 1) load_tile_h(smemh + STAGE_HALFS, Arow, Brow0, Brow1, 64, Kbytes, tid);
    else       CP_COMMIT();

    int buf = 0;
    for (int i = 0; i < T; ++i) {
        CP_WAIT1();
        __syncthreads();
        if (i + 2 < T)
            load_tile_h(smemh + ((buf + 2) % NSTAGE) * STAGE_HALFS,
                        Arow, Brow0, Brow1, (long)(i + 2) * 64, Kbytes, tid);
        else
            CP_COMMIT();

        const __half* Ab = smemh + buf * STAGE_HALFS;
        const __half* Bb = Ab + TILE_A;
#pragma unroll
        for (int ks = 0; ks < 2; ++ks) {     // two k16 slices per 32-half block
            wmma::fragment<wmma::matrix_a, 16, 16, 16, __half, wmma::row_major> af[4];
            wmma::fragment<wmma::matrix_b, 16, 16, 16, __half, wmma::col_major> bf[4];
#pragma unroll
            for (int mt = 0; mt < 4; ++mt)
                wmma::load_matrix_sync(af[mt],
                    Ab + (wm + mt * 16) * AS_STRIDE + ks * 16, AS_STRIDE);
#pragma unroll
            for (int nt = 0; nt < 4; ++nt)
                wmma::load_matrix_sync(bf[nt],
                    Bb + (wn + nt * 16) * AS_STRIDE + ks * 16, AS_STRIDE);
#pragma unroll
            for (int mt = 0; mt < 4; ++mt)
#pragma unroll
                for (int nt = 0; nt < 4; ++nt)
                    wmma::mma_sync(acc[mt][nt], af[mt], bf[nt], acc[mt][nt]);
        }
        buf = (buf + 1) % NSTAGE;
    }
    __syncthreads();

    // epilogue: stage 64 rows at a time through smem (float), coalesced stores
    float* Cs = (float*)smemh;   // 64*256 floats = 64KB <= 90KB
#pragma unroll
    for (int h = 0; h < 2; ++h) {
        if ((wid & 1) == h) {
#pragma unroll
            for (int mt = 0; mt < 4; ++mt)
#pragma unroll
                for (int nt = 0; nt < 4; ++nt)
                    wmma::store_matrix_sync(Cs + (mt * 16) * 256 + wn + nt * 16,
                                            acc[mt][nt], 256, wmma::mem_row_major);
        }
        __syncthreads();
        for (int e = tid; e < 64 * 64; e += 256) {
            int r = e >> 6, c4 = (e & 63) * 4;
            int gm = m0 + h * 64 + r;
            if (gm < M) {
                float4 v = *(const float4*)(Cs + r * 256 + c4);
                int gn = n0 + c4;
                v.x += bias[gn];     v.y += bias[gn + 1];
                v.z += bias[gn + 2]; v.w += bias[gn + 3];
                if (ACT == 0) {
                    __half2 h01 = __floats2half2_rn(geluf(v.x), geluf(v.y));
                    __half2 h23 = __floats2half2_rn(geluf(v.z), geluf(v.w));
                    uint2 u = make_uint2(*(const uint32_t*)&h01,
                                         *(const uint32_t*)&h23);
                    __half* Ch = (__half*)Cv;
                    *(uint2*)(Ch + (size_t)gm * ldc + coff + gn) = u;
                } else {
                    v.x = sigmf(v.x); v.y = sigmf(v.y);
                    v.z = sigmf(v.z); v.w = sigmf(v.w);
                    *(float4*)((float*)Cv + (size_t)gm * ldc + coff + gn) = v;
                }
            }
        }
        __syncthreads();
    }
}

// ---------------- fused gather + conv1 + conv2 + head ----------------
#define CONV_SMEM_FLOATS 25560

// packed-apply: 8 f32x2 accumulators, even pairs PE[0..9], odd pairs PO[0..8],
// 5-tap weights WP. Accumulation order per element identical to scalar version.
#define C2_APPLY2(ACCQ, PE, PO, WP) do {                                    \
    unsigned long long bq;                                                  \
    bq = pack2((WP)[0], (WP)[0]);                                           \
    _Pragma("unroll") for (int t = 0; t < 8; ++t) fma2((ACCQ)[t], (PE)[t], bq); \
    bq = pack2((WP)[1], (WP)[1]);                                           \
    _Pragma("unroll") for (int t = 0; t < 8; ++t) fma2((ACCQ)[t], (PO)[t], bq); \
    bq = pack2((WP)[2], (WP)[2]);                                           \
    _Pragma("unroll") for (int t = 0; t < 8; ++t) fma2((ACCQ)[t], (PE)[t + 1], bq); \
    bq = pack2((WP)[3], (WP)[3]);                                           \
    _Pragma("unroll") for (int t = 0; t < 8; ++t) fma2((ACCQ)[t], (PO)[t + 1], bq); \
    bq = pack2((WP)[4], (WP)[4]);                                           \
    _Pragma("unroll") for (int t = 0; t < 8; ++t) fma2((ACCQ)[t], (PE)[t + 2], bq); \
} while (0)

__global__ void __launch_bounds__(256)
conv_fused(const float* __restrict__ eAll, const int* __restrict__ idx,
           const float* __restrict__ w1, const float* __restrict__ b1,
           const float* __restrict__ w2, const float* __restrict__ b2,
           const float* __restrict__ Wout, const float* __restrict__ bout,
           float* __restrict__ outG, float* __restrict__ flatG)
{
    extern __shared__ float sm[];
    float* flatS = sm;
    float* h1p   = sm + 8192;
    float* w2s   = sm + 16512;
    float* xp    = sm + 24224;
    float* w1s   = sm + 25256;
    float* b1s   = sm + 25496;
    float* b2s   = sm + 25512;
    float* red   = sm + 25544;

    const int tid = threadIdx.x;
    const int b   = blockIdx.x;

    for (int t = tid; t < 7680; t += 256) {
        int oc = t / 240, r = t % 240;
        w2s[oc * 241 + r] = w2[t];
    }
    if (tid < 240) w1s[tid] = w1[tid];
    if (tid < 16) b1s[tid] = b1[tid];
    if (tid < 32) b2s[tid] = b2[tid];

    int id = idx[b];
    int r_no = id / NP, p_no = id % NP;
    const float* rrow = eAll + (size_t)r_no * DCOL;
    const float* prow = eAll + (size_t)(NR + p_no) * DCOL;
    for (int t = tid; t < 1024; t += 256) {
        int rr = t >> 9, c = t & 511;
        xp[rr * 516 + 2 + c] = rr ? prow[c] : rrow[c];
    }
    if (tid < 8) {
        int rr = tid >> 2, q = tid & 3;
        xp[rr * 516 + (q < 2 ? q : 512 + q)] = 0.0f;
    }
    if (tid < 128) {
        int c = tid >> 3, q = tid & 7, ih = q >> 2, pc = q & 3;
        h1p[(c * 2 + ih) * 260 + (pc < 2 ? pc : 256 + pc)] = 0.0f;
    }
    __syncthreads();

    for (int i = 0; i < 32; ++i) {
        int id1 = i * 256 + tid;
        int c = id1 >> 9, rem = id1 & 511, ph = rem >> 8, pw = rem & 255;
        float sum = 0.0f;
#pragma unroll
        for (int dr = 0; dr < 2; ++dr) {
            int oh = 2 * ph + dr;
#pragma unroll
            for (int dc = 0; dc < 2; ++dc) {
                int ow = 2 * pw + dc;
                float v = b1s[c];
                int kh = 2 - oh;
                if (kh >= 0) {
#pragma unroll
                    for (int kw = 0; kw < 5; ++kw)
                        v = fmaf(xp[ow + kw], w1s[c * 15 + kh * 5 + kw], v);
                }
                kh = 3 - oh;
                if (kh < 3) {
#pragma unroll
                    for (int kw = 0; kw < 5; ++kw)
                        v = fmaf(xp[516 + ow + kw], w1s[c * 15 + kh * 5 + kw], v);
                }
                sum += lrelu(v);
            }
        }
        h1p[(c * 2 + ph) * 260 + 2 + pw] = 0.25f * sum;
    }
    __syncthreads();

    // ---- conv2 with packed f32x2 accumulation ----
    {
        const int oc  = tid & 31;
        const int r   = tid >> 5;
        const int ph2 = r >> 2, seg = r & 3;
        const int oh0 = 2 * ph2, oh1 = oh0 + 1;
        const int wbase = oc * 241;
        const float bb = b2s[oc];

#pragma unroll 1
        for (int ch = 0; ch < 4; ++ch) {
            const int ow0 = (seg * 32 + ch * 8) * 2;   // even padded start index
            unsigned long long acc0q[8], acc1q[8];
            const unsigned long long bbq = pack2(bb, bb);
#pragma unroll
            for (int t = 0; t < 8; ++t) { acc0q[t] = bbq; acc1q[t] = bbq; }

#pragma unroll 1
            for (int ic = 0; ic < 16; ++ic) {
                const float2* h0p = (const float2*)(h1p + (ic * 2) * 260 + ow0);
                const float2* h1rp = (const float2*)(h1p + (ic * 2 + 1) * 260 + ow0);
                float2 pe0f[10], pe1f[10];
#pragma unroll
                for (int t = 0; t < 10; ++t) { pe0f[t] = h0p[t]; pe1f[t] = h1rp[t]; }
                unsigned long long pe0[10], pe1[10], po0[9], po1[9];
#pragma unroll
                for (int t = 0; t < 10; ++t) {
                    pe0[t] = pack2(pe0f[t].x, pe0f[t].y);
                    pe1[t] = pack2(pe1f[t].x, pe1f[t].y);
                }
#pragma unroll
                for (int t = 0; t < 9; ++t) {
                    po0[t] = pack2(pe0f[t].y, pe0f[t + 1].x);
                    po1[t] = pack2(pe1f[t].y, pe1f[t + 1].x);
                }

                const float* wrow = &w2s[wbase + ic * 15];
                int kh;
                kh = 2 - oh0;                  // ih=0 -> row oh0
                if (kh >= 0) C2_APPLY2(acc0q, pe0, po0, wrow + kh * 5);
                kh = 2 - oh1;                  // ih=0 -> row oh1
                if (kh >= 0) C2_APPLY2(acc1q, pe0, po0, wrow + kh * 5);
                kh = 3 - oh0;                  // ih=1 -> row oh0
                if (kh >= 0 && kh < 3) C2_APPLY2(acc0q, pe1, po1, wrow + kh * 5);
                kh = 3 - oh1;                  // ih=1 -> row oh1
                if (kh < 3) C2_APPLY2(acc1q, pe1, po1, wrow + kh * 5);
            }

#pragma unroll
            for (int jj = 0; jj < 8; ++jj) {
                float2 a0 = unpack2(acc0q[jj]);
                float2 a1 = unpack2(acc1q[jj]);
                float v00 = lrelu(a0.x), v01 = lrelu(a0.y);
                float v10 = lrelu(a1.x), v11 = lrelu(a1.y);
                float m = fmaxf(fmaxf(v00, v01), fmaxf(v10, v11));
                flatS[oc * 256 + ph2 * 128 + seg * 32 + ch * 8 + jj] = tanh_fast(m);
            }
        }
    }
    __syncthreads();

    float4* fdst = (float4*)(flatG + (size_t)b * 8192);
    const float4* fsrc = (const float4*)flatS;
#pragma unroll
    for (int q = 0; q < 8; ++q) fdst[tid + q * 256] = fsrc[tid + q * 256];

    float p0 = 0.0f, p1 = 0.0f;
    for (int j = tid; j < 8192; j += 256) {
        float f = flatS[j];
        p0 = fmaf(f, Wout[2 * j], p0);
        p1 = fmaf(f, Wout[2 * j + 1], p1);
    }
#pragma unroll
    for (int off = 16; off; off >>= 1) {
        p0 += __shfl_down_sync(0xffffffffu, p0, off);
        p1 += __shfl_down_sync(0xffffffffu, p1, off);
    }
    if ((tid & 31) == 0) { red[2 * (tid >> 5)] = p0; red[2 * (tid >> 5) + 1] = p1; }
    __syncthreads();
    if (tid == 0) {
        float s0 = bout[0], s1 = bout[1];
#pragma unroll
        for (int w = 0; w < 8; ++w) { s0 += red[2 * w]; s1 += red[2 * w + 1]; }
        outG[(size_t)b * 2]     = s0;
        outG[(size_t)b * 2 + 1] = s1;
    }
}

// ---------------- launch ----------------
extern "C" void kernel_launch(void* const* d_in, const int* in_sizes, int n_in,
                              void* d_out, int out_size)
{
    const float* r_att  = (const float*)d_in[0];
    const float* p_att  = (const float*)d_in[1];
    const float* r_fun  = (const float*)d_in[2];
    const float* p_fun  = (const float*)d_in[3];
    const int*   idx    = (const int*)d_in[4];
    const float* W_att1 = (const float*)d_in[5];
    const float* b_att1 = (const float*)d_in[6];
    const float* W_att2 = (const float*)d_in[7];
    const float* b_att2 = (const float*)d_in[8];
    const float* W_fun1 = (const float*)d_in[9];
    const float* b_fun1 = (const float*)d_in[10];
    const float* W_fun2 = (const float*)d_in[11];
    const float* b_fun2 = (const float*)d_in[12];
    const float* c1w    = (const float*)d_in[13];
    const float* c1b    = (const float*)d_in[14];
    const float* c2w    = (const float*)d_in[15];
    const float* c2b    = (const float*)d_in[16];
    const float* Wout   = (const float*)d_in[17];
    const float* bout   = (const float*)d_in[18];
    float* out = (float*)d_out;

    __half *H1, *H2, *AA, *AF, *WT1, *WT2, *WT3, *WT4;
    cudaGetSymbolAddress((void**)&H1,  g_H1);
    cudaGetSymbolAddress((void**)&H2,  g_H2);
    cudaGetSymbolAddress((void**)&AA,  g_AA);
    cudaGetSymbolAddress((void**)&AF,  g_AF);
    cudaGetSymbolAddress((void**)&WT1, g_WT1);
    cudaGetSymbolAddress((void**)&WT2, g_WT2);
    cudaGetSymbolAddress((void**)&WT3, g_WT3);
    cudaGetSymbolAddress((void**)&WT4, g_WT4);

    // prep: float -> half (FUN rows padded to aligned stride)
    pad_copy_h<<<NR, 256>>>(r_att, AA, KATT, KATT);
    pad_copy_h<<<NP, 256>>>(p_att, AA + (size_t)NR * KATT, KATT, KATT);
    pad_copy_h<<<NR, 256>>>(r_fun, AF, KFUN, KFUN_PAD);
    pad_copy_h<<<NP, 256>>>(p_fun, AF + (size_t)NR * KFUN_PAD, KFUN, KFUN_PAD);

    dim3 tb(32, 8);
    transpose_h<<<dim3(94, 64),   tb>>>(W_att1, WT1, KATT, 2048, KATT);
    transpose_h<<<dim3(176, 128), tb>>>(W_fun1, WT2, KFUN, 4096, KFUN_PAD);
    transpose_h<<<dim3(64, 8),    tb>>>(W_att2, WT3, 2048, 256, 2048);
    transpose_h<<<dim3(128, 8),   tb>>>(W_fun2, WT4, 4096, 256, 4096);

    cudaFuncSetAttribute(gemm_h<0>, cudaFuncAttributeMaxDynamicSharedMemorySize, GEMM_SMEM);
    cudaFuncSetAttribute(gemm_h<1>, cudaFuncAttributeMaxDynamicSharedMemorySize, GEMM_SMEM);

    // layer 1 (gelu -> half H) ; grid (m-blocks, n-blocks)
    gemm_h<0><<<dim3(28, 8), 256, GEMM_SMEM>>>(AA, WT1, b_att1,
                                               H1, MROWS, KATT, KATT, KATT, 2048, 0);
    gemm_h<0><<<dim3(28, 16), 256, GEMM_SMEM>>>(AF, WT2, b_fun1,
                                                H2, MROWS, KFUN, KFUN_PAD, KFUN_PAD, 4096, 0);
    // layer 2 (sigmoid -> float) directly into d_out's e region (e_r ++ e_p)
    gemm_h<1><<<dim3(28, 1), 256, GEMM_SMEM>>>(H1, WT3, b_att2,
                                               out, MROWS, 2048, 2048, 2048, DCOL, 0);
    gemm_h<1><<<dim3(28, 1), 256, GEMM_SMEM>>>(H2, WT4, b_fun2,
                                               out, MROWS, 4096, 4096, 4096, DCOL, 256);

    cudaFuncSetAttribute(conv_fused, cudaFuncAttributeMaxDynamicSharedMemorySize,
                         CONV_SMEM_FLOATS * 4);
    conv_fused<<<BBATCH, 256, CONV_SMEM_FLOATS * 4>>>(out, idx, c1w, c1b, c2w, c2b,
                                                      Wout, bout,
                                                      out + OUT_OFF, out + FLAT_OFF);
}

// round 15
// speedup vs baseline: 1.4028x; 1.4028x over previous
#include <cuda_runtime.h>
#include <cuda_fp16.h>
#include <math.h>
#include <stdint.h>
#include <mma.h>

using namespace nvcuda;

// ---------------- problem constants ----------------
#define NR 2000
#define NP 1512
#define MROWS 3512            // NR + NP
#define DCOL 512              // e columns
#define BBATCH 8192
#define E_FLOATS (3512*512)           // 1798144
#define OUT_OFF  E_FLOATS             // output[8192,2]
#define FLAT_OFF (E_FLOATS + 8192*2)  // flat[8192,8192]

#define KATT 3000
#define KFUN 5603
#define KFUN_PAD 5632          // keeps rows 16B-aligned as halves

#define W2R_ELEMS (3 * 5 * 16 * 32)   // 7680 halves

// scratch (allocation-free rule: __device__ globals) — fp16 GEMM operands
__device__ __half g_H1[(size_t)3512 * 2048];
__device__ __half g_H2[(size_t)3512 * 4096];
__device__ __half g_AA[(size_t)3512 * KATT];       // [r_att ; p_att]
__device__ __half g_AF[(size_t)3512 * KFUN_PAD];   // padded [r_fun ; p_fun]
__device__ __half g_WT1[(size_t)2048 * KATT];      // W_att1^T
__device__ __half g_WT2[(size_t)4096 * KFUN_PAD];  // W_fun1^T (padded stride)
__device__ __half g_WT3[(size_t)256 * 2048];       // W_att2^T
__device__ __half g_WT4[(size_t)256 * 4096];       // W_fun2^T
__device__ __half g_W2R[W2R_ELEMS];                // conv2 w reorg [kh][kw][ic][oc]

__device__ __forceinline__ float geluf(float x) {
    return 0.5f * x * (1.0f + erff(x * 0.70710678118654752440f));
}
__device__ __forceinline__ float sigmf(float x) {
    return 1.0f / (1.0f + expf(-x));
}
__device__ __forceinline__ float lrelu(float x) {
    return (x >= 0.0f) ? x : 0.01f * x;
}
__device__ __forceinline__ float tanh_fast(float x) {
    float y;
    asm("tanh.approx.f32 %0, %1;" : "=f"(y) : "f"(x));
    return y;
}

#define CP_ASYNC16(dst, src, sz) \
    asm volatile("cp.async.cg.shared.global [%0], [%1], 16, %2;" \
        :: "r"(dst), "l"(src), "r"(sz))
#define CP_COMMIT() asm volatile("cp.async.commit_group;" ::: "memory")
#define CP_WAIT1()  asm volatile("cp.async.wait_group 1;" ::: "memory")

__device__ __forceinline__ uint32_t smem_u32(const void* p) {
    uint32_t a;
    asm("{ .reg .u64 t; cvta.to.shared.u64 t, %1; cvt.u32.u64 %0, t; }" : "=r"(a) : "l"(p));
    return a;
}

// ---------------- padded copy float -> half ----------------
__global__ void pad_copy_h(const float* __restrict__ src, __half* __restrict__ dst,
                           int K, int ldd)
{
    int r = blockIdx.x;
    const float* s = src + (size_t)r * K;
    __half* d = dst + (size_t)r * ldd;
    for (int c = threadIdx.x; c < K; c += blockDim.x)
        d[c] = __float2half_rn(s[c]);
}

// ---------------- conv2 weight reorg: W2R[kh][kw][ic][oc] = w2[oc][ic][kh][kw] ----------------
__global__ void reorg_w2(const float* __restrict__ w2, __half* __restrict__ out)
{
    int t = blockIdx.x * blockDim.x + threadIdx.x;
    if (t >= W2R_ELEMS) return;
    int oc = t & 31, r = t >> 5;       // r = (kh*5+kw)*16 + ic, 0..239
    int ic = r & 15, q = r >> 4;       // q = kh*5 + kw, 0..14
    int kh = q / 5, kw = q % 5;
    out[t] = __float2half_rn(w2[((oc * 16 + ic) * 3 + kh) * 5 + kw]);
}

// ---------------- weight transpose float -> half: out[n*ldo+k] = in[k*N+n] ----------------
__global__ void transpose_h(const float* __restrict__ in, __half* __restrict__ out,
                            int K, int N, int ldo)
{
    __shared__ float t[32][33];
    int k0 = blockIdx.x * 32, n0 = blockIdx.y * 32;
    int x = threadIdx.x, y = threadIdx.y;   // 32 x 8
#pragma unroll
    for (int r = 0; r < 32; r += 8) {
        int k = k0 + y + r, n = n0 + x;
        t[y + r][x] = (k < K && n < N) ? in[(size_t)k * N + n] : 0.0f;
    }
    __syncthreads();
#pragma unroll
    for (int r = 0; r < 32; r += 8) {
        int n = n0 + y + r, k = k0 + x;
        if (n < N && k < K) out[(size_t)n * ldo + k] = __float2half_rn(t[x][y + r]);
    }
}

// ---------------- wmma fp16 GEMM, CTA tile 128x256x32, warp tile 64x64 ----------------
#define AS_STRIDE 40                 // halves; 80B row stride
#define TILE_A (128 * AS_STRIDE)     // 5120 halves
#define TILE_B (256 * AS_STRIDE)     // 10240 halves
#define STAGE_HALFS (TILE_A + TILE_B)            // 15360 halves = 30720 B
#define NSTAGE 3
#define GEMM_SMEM (NSTAGE * STAGE_HALFS * 2)     // 92160 B

__device__ __forceinline__ void load_tile_h(__half* stage,
                                            const char* Arow,
                                            const char* Brow0, const char* Brow1,
                                            long kb, long Kbytes, int tid)
{
    __half* As = stage;
    __half* Bs = stage + TILE_A;
    const int row = tid >> 1;            // 0..127
    const int cb0 = (tid & 1) * 32;      // byte offset within the 64B row chunk
    uint32_t dA  = smem_u32(As + row * AS_STRIDE) + cb0;
    uint32_t dB0 = smem_u32(Bs + row * AS_STRIDE) + cb0;
    uint32_t dB1 = smem_u32(Bs + (row + 128) * AS_STRIDE) + cb0;
#pragma unroll
    for (int c = 0; c < 2; ++c) {
        long off = kb + cb0 + c * 16;
        long rem = Kbytes - off;
        int sz = rem >= 16 ? 16 : (rem > 0 ? (int)rem : 0);
        CP_ASYNC16(dA + c * 16, Arow + off, sz);
        CP_ASYNC16(dB0 + c * 16, Brow0 + off, sz);
        CP_ASYNC16(dB1 + c * 16, Brow1 + off, sz);
    }
    CP_COMMIT();
}

template <int ACT>   // 0 = gelu -> half, 1 = sigmoid -> float
__global__ void __launch_bounds__(256, 1)
gemm_h(const __half* __restrict__ A, const __half* __restrict__ BT,
       const float* __restrict__ bias, void* __restrict__ Cv,
       int M, int K, int lda, int ldb, int ldc, int coff)
{
    extern __shared__ __half smemh[];

    const int tid = threadIdx.x;
    const int wid = tid >> 5;
    const int wm = (wid & 1) * 64;
    const int wn = (wid >> 1) * 64;
    const int m0 = blockIdx.x * 128, n0 = blockIdx.y * 256;

    int gr = m0 + (tid >> 1); if (gr >= M) gr = M - 1;
    const char* Arow  = (const char*)(A + (size_t)gr * lda);
    const char* Brow0 = (const char*)(BT + (size_t)(n0 + (tid >> 1)) * ldb);
    const char* Brow1 = (const char*)(BT + (size_t)(n0 + (tid >> 1) + 128) * ldb);
    const long Kbytes = (long)K * 2;
    const int T = (K + 31) / 32;

    wmma::fragment<wmma::accumulator, 16, 16, 16, float> acc[4][4];
#pragma unroll
    for (int mt = 0; mt < 4; ++mt)
#pragma unroll
        for (int nt = 0; nt < 4; ++nt)
            wmma::fill_fragment(acc[mt][nt], 0.0f);

    load_tile_h(smemh, Arow, Brow0, Brow1, 0, Kbytes, tid);
    if (T > 1) load_tile_h(smemh + STAGE_HALFS, Arow, Brow0, Brow1, 64, Kbytes, tid);
    else       CP_COMMIT();

    int buf = 0;
    for (int i = 0; i < T; ++i) {
        CP_WAIT1();
        __syncthreads();
        if (i + 2 < T)
            load_tile_h(smemh + ((buf + 2) % NSTAGE) * STAGE_HALFS,
                        Arow, Brow0, Brow1, (long)(i + 2) * 64, Kbytes, tid);
        else
            CP_COMMIT();

        const __half* Ab = smemh + buf * STAGE_HALFS;
        const __half* Bb = Ab + TILE_A;
#pragma unroll
        for (int ks = 0; ks < 2; ++ks) {
            wmma::fragment<wmma::matrix_a, 16, 16, 16, __half, wmma::row_major> af[4];
            wmma::fragment<wmma::matrix_b, 16, 16, 16, __half, wmma::col_major> bf[4];
#pragma unroll
            for (int mt = 0; mt < 4; ++mt)
                wmma::load_matrix_sync(af[mt],
                    Ab + (wm + mt * 16) * AS_STRIDE + ks * 16, AS_STRIDE);
#pragma unroll
            for (int nt = 0; nt < 4; ++nt)
                wmma::load_matrix_sync(bf[nt],
                    Bb + (wn + nt * 16) * AS_STRIDE + ks * 16, AS_STRIDE);
#pragma unroll
            for (int mt = 0; mt < 4; ++mt)
#pragma unroll
                for (int nt = 0; nt < 4; ++nt)
                    wmma::mma_sync(acc[mt][nt], af[mt], bf[nt], acc[mt][nt]);
        }
        buf = (buf + 1) % NSTAGE;
    }
    __syncthreads();

    float* Cs = (float*)smemh;
#pragma unroll
    for (int h = 0; h < 2; ++h) {
        if ((wid & 1) == h) {
#pragma unroll
            for (int mt = 0; mt < 4; ++mt)
#pragma unroll
                for (int nt = 0; nt < 4; ++nt)
                    wmma::store_matrix_sync(Cs + (mt * 16) * 256 + wn + nt * 16,
                                            acc[mt][nt], 256, wmma::mem_row_major);
        }
        __syncthreads();
        for (int e = tid; e < 64 * 64; e += 256) {
            int r = e >> 6, c4 = (e & 63) * 4;
            int gm = m0 + h * 64 + r;
            if (gm < M) {
                float4 v = *(const float4*)(Cs + r * 256 + c4);
                int gn = n0 + c4;
                v.x += bias[gn];     v.y += bias[gn + 1];
                v.z += bias[gn + 2]; v.w += bias[gn + 3];
                if (ACT == 0) {
                    __half2 h01 = __floats2half2_rn(geluf(v.x), geluf(v.y));
                    __half2 h23 = __floats2half2_rn(geluf(v.z), geluf(v.w));
                    uint2 u = make_uint2(*(const uint32_t*)&h01,
                                         *(const uint32_t*)&h23);
                    __half* Ch = (__half*)Cv;
                    *(uint2*)(Ch + (size_t)gm * ldc + coff + gn) = u;
                } else {
                    v.x = sigmf(v.x); v.y = sigmf(v.y);
                    v.z = sigmf(v.z); v.w = sigmf(v.w);
                    *(float4*)((float*)Cv + (size_t)gm * ldc + coff + gn) = v;
                }
            }
        }
        __syncthreads();
    }
}

// ---------------- fused gather + conv1 + tensor-core conv2 + head ----------------
// smem layout (float offsets):
//   flatS : 8192        @ 0
//   xp    : 2*516       @ 8192     (gathered e-rows, fp32, W-pad 2)
//   XPh   : 2*260*16 h  @ 9224     (conv1 out, fp16 channel-last, W-pad 2)  [4160 f]
//   W2R   : 7680 h      @ 13384    (conv2 weights [kh][kw][ic][oc])         [3840 f]
//   S     : 8*512       @ 17224    (per-warp pool staging [2][16][16] f32)
//   w1s   : 240         @ 21320
//   b1s   : 16          @ 21560
//   b2s   : 32          @ 21576
//   red   : 16          @ 21608
#define CONV_SMEM_FLOATS 21624

__global__ void __launch_bounds__(256)
conv_fused(const float* __restrict__ eAll, const int* __restrict__ idx,
           const float* __restrict__ w1, const float* __restrict__ b1,
           const __half* __restrict__ w2r, const float* __restrict__ b2,
           const float* __restrict__ Wout, const float* __restrict__ bout,
           float* __restrict__ outG, float* __restrict__ flatG)
{
    extern __shared__ float sm[];
    float* flatS = sm;
    float* xp    = sm + 8192;
    __half* XPh  = (__half*)(sm + 9224);
    __half* W2Rs = (__half*)(sm + 13384);
    float* sS    = sm + 17224;
    float* w1s   = sm + 21320;
    float* b1s   = sm + 21560;
    float* b2s   = sm + 21576;
    float* red   = sm + 21608;

    const int tid = threadIdx.x;
    const int b   = blockIdx.x;

    // ---- weights into smem ----
    for (int t = tid; t < W2R_ELEMS; t += 256) W2Rs[t] = w2r[t];
    if (tid < 240) w1s[tid] = w1[tid];
    if (tid < 16) b1s[tid] = b1[tid];
    if (tid < 32) b2s[tid] = b2[tid];

    // ---- gather the two e rows into padded xp[2][516] ----
    int id = idx[b];
    int r_no = id / NP, p_no = id % NP;
    const float* rrow = eAll + (size_t)r_no * DCOL;
    const float* prow = eAll + (size_t)(NR + p_no) * DCOL;
    for (int t = tid; t < 1024; t += 256) {
        int rr = t >> 9, c = t & 511;
        xp[rr * 516 + 2 + c] = rr ? prow[c] : rrow[c];
    }
    if (tid < 8) {
        int rr = tid >> 2, q = tid & 3;
        xp[rr * 516 + (q < 2 ? q : 512 + q)] = 0.0f;
    }
    // zero W-pads of XPh: pc in {0,1,258,259}, ih in {0,1}, c in 0..15
    if (tid < 128) {
        int c = tid & 15, rest = tid >> 4;       // rest 0..7
        int ih = rest >> 2, pcidx = rest & 3;
        int pc = (pcidx < 2) ? pcidx : 256 + pcidx;
        XPh[ih * 4160 + pc * 16 + c] = __float2half_rn(0.0f);
    }
    __syncthreads();

    // ---- conv1 (16ch, 3x5, pad 2) + leaky + avgpool2 -> XPh[ih][2+pw][c] fp16 ----
    for (int i = 0; i < 32; ++i) {
        int id1 = i * 256 + tid;
        int c = id1 >> 9, rem = id1 & 511, ph = rem >> 8, pw = rem & 255;
        float sum = 0.0f;
#pragma unroll
        for (int dr = 0; dr < 2; ++dr) {
            int oh = 2 * ph + dr;
#pragma unroll
            for (int dc = 0; dc < 2; ++dc) {
                int ow = 2 * pw + dc;
                float v = b1s[c];
                int kh = 2 - oh;
                if (kh >= 0) {
#pragma unroll
                    for (int kw = 0; kw < 5; ++kw)
                        v = fmaf(xp[ow + kw], w1s[c * 15 + kh * 5 + kw], v);
                }
                kh = 3 - oh;
                if (kh < 3) {
#pragma unroll
                    for (int kw = 0; kw < 5; ++kw)
                        v = fmaf(xp[516 + ow + kw], w1s[c * 15 + kh * 5 + kw], v);
                }
                sum += lrelu(v);
            }
        }
        XPh[ph * 4160 + (2 + pw) * 16 + c] = __float2half_rn(0.25f * sum);
    }
    __syncthreads();

    // ---- conv2 via wmma implicit GEMM + bias + leaky + maxpool2 + tanh ----
    // warp w: ph2 = w&1 (pool row), ntile = (w>>1)&1 (oc half), mhalf = w>>2.
    // acc0 = conv row oh=2*ph2, acc1 = oh=2*ph2+1. Valid taps only.
    {
        const int w    = tid >> 5;
        const int lane = tid & 31;
        const int ph2   = w & 1;
        const int ntile = (w >> 1) & 1;
        const int mhalf = w >> 2;
        float* S = sS + w * 512;       // [2][16][16]

        const int khA = ph2 ? 0 : 1;   // lower kh of this pair
        wmma::fragment<wmma::matrix_b, 16, 16, 16, __half, wmma::row_major> bA[5], bB[5];
#pragma unroll
        for (int kw = 0; kw < 5; ++kw) {
            wmma::load_matrix_sync(bA[kw],
                W2Rs + ((khA * 5 + kw) * 16) * 32 + ntile * 16, 32);
            wmma::load_matrix_sync(bB[kw],
                W2Rs + (((khA + 1) * 5 + kw) * 16) * 32 + ntile * 16, 32);
        }

#pragma unroll 1
        for (int j = 0; j < 8; ++j) {
            const int mt = mhalf * 8 + j;          // m-tile: ow base mt*16
            wmma::fragment<wmma::accumulator, 16, 16, 16, float> acc0, acc1;
            wmma::fill_fragment(acc0, 0.0f);
            wmma::fill_fragment(acc1, 0.0f);

#pragma unroll
            for (int kw = 0; kw < 5; ++kw) {
                wmma::fragment<wmma::matrix_a, 16, 16, 16, __half, wmma::row_major> a;
                const __half* base = XPh + (mt * 16 + kw) * 16;
                if (ph2 == 0) {
                    // acc0 (oh0): kh2/ih0 ; acc1 (oh1): kh1/ih0, kh2/ih1
                    wmma::load_matrix_sync(a, base, 16);              // ih0
                    wmma::mma_sync(acc0, a, bB[kw], acc0);
                    wmma::mma_sync(acc1, a, bA[kw], acc1);
                    wmma::load_matrix_sync(a, base + 4160, 16);       // ih1
                    wmma::mma_sync(acc1, a, bB[kw], acc1);
                } else {
                    // acc0 (oh2): kh0/ih0, kh1/ih1 ; acc1 (oh3): kh0/ih1
                    wmma::load_matrix_sync(a, base, 16);              // ih0
                    wmma::mma_sync(acc0, a, bA[kw], acc0);
                    wmma::load_matrix_sync(a, base + 4160, 16);       // ih1
                    wmma::mma_sync(acc0, a, bB[kw], acc0);
                    wmma::mma_sync(acc1, a, bA[kw], acc1);
                }
            }

            wmma::store_matrix_sync(S,       acc0, 16, wmma::mem_row_major);
            wmma::store_matrix_sync(S + 256, acc1, 16, wmma::mem_row_major);
            __syncwarp();

#pragma unroll
            for (int q = 0; q < 4; ++q) {
                int p = q * 32 + lane;           // 0..127
                int n = p & 15, w2c = p >> 4;    // oc-local, pooled col 0..7
                float bias = b2s[ntile * 16 + n];
                int m0i = 2 * w2c * 16 + n;
                float v00 = lrelu(S[m0i] + bias);
                float v01 = lrelu(S[m0i + 16] + bias);
                float v10 = lrelu(S[256 + m0i] + bias);
                float v11 = lrelu(S[256 + m0i + 16] + bias);
                float m = fmaxf(fmaxf(v00, v01), fmaxf(v10, v11));
                flatS[(ntile * 16 + n) * 256 + ph2 * 128 + mt * 8 + w2c] = tanh_fast(m);
            }
            __syncwarp();
        }
    }
    __syncthreads();

    // ---- coalesced flat store ----
    float4* fdst = (float4*)(flatG + (size_t)b * 8192);
    const float4* fsrc = (const float4*)flatS;
#pragma unroll
    for (int q = 0; q < 8; ++q) fdst[tid + q * 256] = fsrc[tid + q * 256];

    // ---- head: out = flat @ W_out + b_out ----
    float p0 = 0.0f, p1 = 0.0f;
    for (int j = tid; j < 8192; j += 256) {
        float f = flatS[j];
        p0 = fmaf(f, Wout[2 * j], p0);
        p1 = fmaf(f, Wout[2 * j + 1], p1);
    }
#pragma unroll
    for (int off = 16; off; off >>= 1) {
        p0 += __shfl_down_sync(0xffffffffu, p0, off);
        p1 += __shfl_down_sync(0xffffffffu, p1, off);
    }
    if ((tid & 31) == 0) { red[2 * (tid >> 5)] = p0; red[2 * (tid >> 5) + 1] = p1; }
    __syncthreads();
    if (tid == 0) {
        float s0 = bout[0], s1 = bout[1];
#pragma unroll
        for (int wq = 0; wq < 8; ++wq) { s0 += red[2 * wq]; s1 += red[2 * wq + 1]; }
        outG[(size_t)b * 2]     = s0;
        outG[(size_t)b * 2 + 1] = s1;
    }
}

// ---------------- launch ----------------
extern "C" void kernel_launch(void* const* d_in, const int* in_sizes, int n_in,
                              void* d_out, int out_size)
{
    const float* r_att  = (const float*)d_in[0];
    const float* p_att  = (const float*)d_in[1];
    const float* r_fun  = (const float*)d_in[2];
    const float* p_fun  = (const float*)d_in[3];
    const int*   idx    = (const int*)d_in[4];
    const float* W_att1 = (const float*)d_in[5];
    const float* b_att1 = (const float*)d_in[6];
    const float* W_att2 = (const float*)d_in[7];
    const float* b_att2 = (const float*)d_in[8];
    const float* W_fun1 = (const float*)d_in[9];
    const float* b_fun1 = (const float*)d_in[10];
    const float* W_fun2 = (const float*)d_in[11];
    const float* b_fun2 = (const float*)d_in[12];
    const float* c1w    = (const float*)d_in[13];
    const float* c1b    = (const float*)d_in[14];
    const float* c2w    = (const float*)d_in[15];
    const float* c2b    = (const float*)d_in[16];
    const float* Wout   = (const float*)d_in[17];
    const float* bout   = (const float*)d_in[18];
    float* out = (float*)d_out;

    __half *H1, *H2, *AA, *AF, *WT1, *WT2, *WT3, *WT4, *W2R;
    cudaGetSymbolAddress((void**)&H1,  g_H1);
    cudaGetSymbolAddress((void**)&H2,  g_H2);
    cudaGetSymbolAddress((void**)&AA,  g_AA);
    cudaGetSymbolAddress((void**)&AF,  g_AF);
    cudaGetSymbolAddress((void**)&WT1, g_WT1);
    cudaGetSymbolAddress((void**)&WT2, g_WT2);
    cudaGetSymbolAddress((void**)&WT3, g_WT3);
    cudaGetSymbolAddress((void**)&WT4, g_WT4);
    cudaGetSymbolAddress((void**)&W2R, g_W2R);

    // prep: float -> half (FUN rows padded), conv2 weight reorg
    pad_copy_h<<<NR, 256>>>(r_att, AA, KATT, KATT);
    pad_copy_h<<<NP, 256>>>(p_att, AA + (size_t)NR * KATT, KATT, KATT);
    pad_copy_h<<<NR, 256>>>(r_fun, AF, KFUN, KFUN_PAD);
    pad_copy_h<<<NP, 256>>>(p_fun, AF + (size_t)NR * KFUN_PAD, KFUN, KFUN_PAD);
    reorg_w2<<<(W2R_ELEMS + 255) / 256, 256>>>(c2w, W2R);

    dim3 tb(32, 8);
    transpose_h<<<dim3(94, 64),   tb>>>(W_att1, WT1, KATT, 2048, KATT);
    transpose_h<<<dim3(176, 128), tb>>>(W_fun1, WT2, KFUN, 4096, KFUN_PAD);
    transpose_h<<<dim3(64, 8),    tb>>>(W_att2, WT3, 2048, 256, 2048);
    transpose_h<<<dim3(128, 8),   tb>>>(W_fun2, WT4, 4096, 256, 4096);

    cudaFuncSetAttribute(gemm_h<0>, cudaFuncAttributeMaxDynamicSharedMemorySize, GEMM_SMEM);
    cudaFuncSetAttribute(gemm_h<1>, cudaFuncAttributeMaxDynamicSharedMemorySize, GEMM_SMEM);

    // layer 1 (gelu -> half H)
    gemm_h<0><<<dim3(28, 8), 256, GEMM_SMEM>>>(AA, WT1, b_att1,
                                               H1, MROWS, KATT, KATT, KATT, 2048, 0);
    gemm_h<0><<<dim3(28, 16), 256, GEMM_SMEM>>>(AF, WT2, b_fun1,
                                                H2, MROWS, KFUN, KFUN_PAD, KFUN_PAD, 4096, 0);
    // layer 2 (sigmoid -> float) directly into d_out's e region
    gemm_h<1><<<dim3(28, 1), 256, GEMM_SMEM>>>(H1, WT3, b_att2,
                                               out, MROWS, 2048, 2048, 2048, DCOL, 0);
    gemm_h<1><<<dim3(28, 1), 256, GEMM_SMEM>>>(H2, WT4, b_fun2,
                                               out, MROWS, 4096, 4096, 4096, DCOL, 256);

    cudaFuncSetAttribute(conv_fused, cudaFuncAttributeMaxDynamicSharedMemorySize,
                         CONV_SMEM_FLOATS * 4);
    conv_fused<<<BBATCH, 256, CONV_SMEM_FLOATS * 4>>>(out, idx, c1w, c1b, W2R, c2b,
                                                      Wout, bout,
                                                      out + OUT_OFF, out + FLAT_OFF);
}

// round 16
// speedup vs baseline: 1.4952x; 1.0659x over previous
#include <cuda_runtime.h>
#include <cuda_fp16.h>
#include <math.h>
#include <stdint.h>
#include <mma.h>

using namespace nvcuda;

// ---------------- problem constants ----------------
#define NR 2000
#define NP 1512
#define MROWS 3512            // NR + NP
#define DCOL 512              // e columns
#define BBATCH 8192
#define E_FLOATS (3512*512)           // 1798144
#define OUT_OFF  E_FLOATS             // output[8192,2]
#define FLAT_OFF (E_FLOATS + 8192*2)  // flat[8192,8192]

#define KATT 3000
#define KFUN 5603
#define KFUN_PAD 5632          // keeps rows 16B-aligned as halves

#define W2R_ELEMS (3 * 5 * 16 * 32)   // 7680 halves

// scratch (allocation-free rule: __device__ globals) — fp16 GEMM operands
__device__ __half g_H1[(size_t)3512 * 2048];
__device__ __half g_H2[(size_t)3512 * 4096];
__device__ __half g_AA[(size_t)3512 * KATT];       // [r_att ; p_att]
__device__ __half g_AF[(size_t)3512 * KFUN_PAD];   // padded [r_fun ; p_fun]
__device__ __half g_WT1[(size_t)2048 * KATT];      // W_att1^T
__device__ __half g_WT2[(size_t)4096 * KFUN_PAD];  // W_fun1^T (padded stride)
__device__ __half g_WT3[(size_t)256 * 2048];       // W_att2^T
__device__ __half g_WT4[(size_t)256 * 4096];       // W_fun2^T
__device__ __half g_W2R[W2R_ELEMS];                // conv2 w reorg [kh][kw][ic][oc]

__device__ __forceinline__ float geluf(float x) {
    return 0.5f * x * (1.0f + erff(x * 0.70710678118654752440f));
}
__device__ __forceinline__ float sigmf(float x) {
    return 1.0f / (1.0f + expf(-x));
}
__device__ __forceinline__ float lrelu(float x) {
    return (x >= 0.0f) ? x : 0.01f * x;
}
__device__ __forceinline__ float tanh_fast(float x) {
    float y;
    asm("tanh.approx.f32 %0, %1;" : "=f"(y) : "f"(x));
    return y;
}

#define CP_ASYNC16(dst, src, sz) \
    asm volatile("cp.async.cg.shared.global [%0], [%1], 16, %2;" \
        :: "r"(dst), "l"(src), "r"(sz))
#define CP_COMMIT() asm volatile("cp.async.commit_group;" ::: "memory")
#define CP_WAIT1()  asm volatile("cp.async.wait_group 1;" ::: "memory")

__device__ __forceinline__ uint32_t smem_u32(const void* p) {
    uint32_t a;
    asm("{ .reg .u64 t; cvta.to.shared.u64 t, %1; cvt.u32.u64 %0, t; }" : "=r"(a) : "l"(p));
    return a;
}

// ---------------- padded copy float -> half ----------------
__global__ void pad_copy_h(const float* __restrict__ src, __half* __restrict__ dst,
                           int K, int ldd)
{
    int r = blockIdx.x;
    const float* s = src + (size_t)r * K;
    __half* d = dst + (size_t)r * ldd;
    for (int c = threadIdx.x; c < K; c += blockDim.x)
        d[c] = __float2half_rn(s[c]);
}

// ---------------- conv2 weight reorg: W2R[kh][kw][ic][oc] = w2[oc][ic][kh][kw] ----------------
__global__ void reorg_w2(const float* __restrict__ w2, __half* __restrict__ out)
{
    int t = blockIdx.x * blockDim.x + threadIdx.x;
    if (t >= W2R_ELEMS) return;
    int oc = t & 31, r = t >> 5;       // r = (kh*5+kw)*16 + ic, 0..239
    int ic = r & 15, q = r >> 4;       // q = kh*5 + kw, 0..14
    int kh = q / 5, kw = q % 5;
    out[t] = __float2half_rn(w2[((oc * 16 + ic) * 3 + kh) * 5 + kw]);
}

// ---------------- weight transpose float -> half: out[n*ldo+k] = in[k*N+n] ----------------
__global__ void transpose_h(const float* __restrict__ in, __half* __restrict__ out,
                            int K, int N, int ldo)
{
    __shared__ float t[32][33];
    int k0 = blockIdx.x * 32, n0 = blockIdx.y * 32;
    int x = threadIdx.x, y = threadIdx.y;   // 32 x 8
#pragma unroll
    for (int r = 0; r < 32; r += 8) {
        int k = k0 + y + r, n = n0 + x;
        t[y + r][x] = (k < K && n < N) ? in[(size_t)k * N + n] : 0.0f;
    }
    __syncthreads();
#pragma unroll
    for (int r = 0; r < 32; r += 8) {
        int n = n0 + y + r, k = k0 + x;
        if (n < N && k < K) out[(size_t)n * ldo + k] = __float2half_rn(t[x][y + r]);
    }
}

// ---------------- wmma fp16 GEMM, CTA tile 128x256x32, warp tile 64x64 ----------------
#define AS_STRIDE 40                 // halves; 80B row stride
#define TILE_A (128 * AS_STRIDE)     // 5120 halves
#define TILE_B (256 * AS_STRIDE)     // 10240 halves
#define STAGE_HALFS (TILE_A + TILE_B)            // 15360 halves = 30720 B
#define NSTAGE 3
#define GEMM_SMEM (NSTAGE * STAGE_HALFS * 2)     // 92160 B

__device__ __forceinline__ void load_tile_h(__half* stage,
                                            const char* Arow,
                                            const char* Brow0, const char* Brow1,
                                            long kb, long Kbytes, int tid)
{
    __half* As = stage;
    __half* Bs = stage + TILE_A;
    const int row = tid >> 1;            // 0..127
    const int cb0 = (tid & 1) * 32;      // byte offset within the 64B row chunk
    uint32_t dA  = smem_u32(As + row * AS_STRIDE) + cb0;
    uint32_t dB0 = smem_u32(Bs + row * AS_STRIDE) + cb0;
    uint32_t dB1 = smem_u32(Bs + (row + 128) * AS_STRIDE) + cb0;
#pragma unroll
    for (int c = 0; c < 2; ++c) {
        long off = kb + cb0 + c * 16;
        long rem = Kbytes - off;
        int sz = rem >= 16 ? 16 : (rem > 0 ? (int)rem : 0);
        CP_ASYNC16(dA + c * 16, Arow + off, sz);
        CP_ASYNC16(dB0 + c * 16, Brow0 + off, sz);
        CP_ASYNC16(dB1 + c * 16, Brow1 + off, sz);
    }
    CP_COMMIT();
}

template <int ACT>   // 0 = gelu -> half, 1 = sigmoid -> float
__global__ void __launch_bounds__(256, 1)
gemm_h(const __half* __restrict__ A, const __half* __restrict__ BT,
       const float* __restrict__ bias, void* __restrict__ Cv,
       int M, int K, int lda, int ldb, int ldc, int coff)
{
    extern __shared__ __half smemh[];

    const int tid = threadIdx.x;
    const int wid = tid >> 5;
    const int wm = (wid & 1) * 64;
    const int wn = (wid >> 1) * 64;
    const int m0 = blockIdx.x * 128, n0 = blockIdx.y * 256;

    int gr = m0 + (tid >> 1); if (gr >= M) gr = M - 1;
    const char* Arow  = (const char*)(A + (size_t)gr * lda);
    const char* Brow0 = (const char*)(BT + (size_t)(n0 + (tid >> 1)) * ldb);
    const char* Brow1 = (const char*)(BT + (size_t)(n0 + (tid >> 1) + 128) * ldb);
    const long Kbytes = (long)K * 2;
    const int T = (K + 31) / 32;

    wmma::fragment<wmma::accumulator, 16, 16, 16, float> acc[4][4];
#pragma unroll
    for (int mt = 0; mt < 4; ++mt)
#pragma unroll
        for (int nt = 0; nt < 4; ++nt)
            wmma::fill_fragment(acc[mt][nt], 0.0f);

    load_tile_h(smemh, Arow, Brow0, Brow1, 0, Kbytes, tid);
    if (T > 1) load_tile_h(smemh + STAGE_HALFS, Arow, Brow0, Brow1, 64, Kbytes, tid);
    else       CP_COMMIT();

    int buf = 0;
    for (int i = 0; i < T; ++i) {
        CP_WAIT1();
        __syncthreads();
        if (i + 2 < T)
            load_tile_h(smemh + ((buf + 2) % NSTAGE) * STAGE_HALFS,
                        Arow, Brow0, Brow1, (long)(i + 2) * 64, Kbytes, tid);
        else
            CP_COMMIT();

        const __half* Ab = smemh + buf * STAGE_HALFS;
        const __half* Bb = Ab + TILE_A;
#pragma unroll
        for (int ks = 0; ks < 2; ++ks) {
            wmma::fragment<wmma::matrix_a, 16, 16, 16, __half, wmma::row_major> af[4];
            wmma::fragment<wmma::matrix_b, 16, 16, 16, __half, wmma::col_major> bf[4];
#pragma unroll
            for (int mt = 0; mt < 4; ++mt)
                wmma::load_matrix_sync(af[mt],
                    Ab + (wm + mt * 16) * AS_STRIDE + ks * 16, AS_STRIDE);
#pragma unroll
            for (int nt = 0; nt < 4; ++nt)
                wmma::load_matrix_sync(bf[nt],
                    Bb + (wn + nt * 16) * AS_STRIDE + ks * 16, AS_STRIDE);
#pragma unroll
            for (int mt = 0; mt < 4; ++mt)
#pragma unroll
                for (int nt = 0; nt < 4; ++nt)
                    wmma::mma_sync(acc[mt][nt], af[mt], bf[nt], acc[mt][nt]);
        }
        buf = (buf + 1) % NSTAGE;
    }
    __syncthreads();

    float* Cs = (float*)smemh;
#pragma unroll
    for (int h = 0; h < 2; ++h) {
        if ((wid & 1) == h) {
#pragma unroll
            for (int mt = 0; mt < 4; ++mt)
#pragma unroll
                for (int nt = 0; nt < 4; ++nt)
                    wmma::store_matrix_sync(Cs + (mt * 16) * 256 + wn + nt * 16,
                                            acc[mt][nt], 256, wmma::mem_row_major);
        }
        __syncthreads();
        for (int e = tid; e < 64 * 64; e += 256) {
            int r = e >> 6, c4 = (e & 63) * 4;
            int gm = m0 + h * 64 + r;
            if (gm < M) {
                float4 v = *(const float4*)(Cs + r * 256 + c4);
                int gn = n0 + c4;
                v.x += bias[gn];     v.y += bias[gn + 1];
                v.z += bias[gn + 2]; v.w += bias[gn + 3];
                if (ACT == 0) {
                    __half2 h01 = __floats2half2_rn(geluf(v.x), geluf(v.y));
                    __half2 h23 = __floats2half2_rn(geluf(v.z), geluf(v.w));
                    uint2 u = make_uint2(*(const uint32_t*)&h01,
                                         *(const uint32_t*)&h23);
                    __half* Ch = (__half*)Cv;
                    *(uint2*)(Ch + (size_t)gm * ldc + coff + gn) = u;
                } else {
                    v.x = sigmf(v.x); v.y = sigmf(v.y);
                    v.z = sigmf(v.z); v.w = sigmf(v.w);
                    *(float4*)((float*)Cv + (size_t)gm * ldc + coff + gn) = v;
                }
            }
        }
        __syncthreads();
    }
}

// ---------------- fused gather + conv1 + tensor-core conv2 + head ----------------
// smem layout (float offsets):
//   flatS : 8192        @ 0
//   xp    : 2*516       @ 8192     (gathered e-rows, fp32, W-pad 2)
//   XPh   : 2*260*16 h  @ 9224     (conv1 out, fp16 channel-last, W-pad 2)  [4160 f]
//   W2R   : 7680 h      @ 13384    (conv2 weights [kh][kw][ic][oc])         [3840 f]
//   S     : 8*512       @ 17224    (per-warp pool staging [2][16][16] f32)
//   w1s   : 240         @ 21320
//   b1s   : 16          @ 21560
//   b2s   : 32          @ 21576
//   red   : 16          @ 21608
#define CONV_SMEM_FLOATS 21624

__global__ void __launch_bounds__(256)
conv_fused(const float* __restrict__ eAll, const int* __restrict__ idx,
           const float* __restrict__ w1, const float* __restrict__ b1,
           const __half* __restrict__ w2r, const float* __restrict__ b2,
           const float* __restrict__ Wout, const float* __restrict__ bout,
           float* __restrict__ outG, float* __restrict__ flatG)
{
    extern __shared__ float sm[];
    float* flatS = sm;
    float* xp    = sm + 8192;
    __half* XPh  = (__half*)(sm + 9224);
    __half* W2Rs = (__half*)(sm + 13384);
    float* sS    = sm + 17224;
    float* w1s   = sm + 21320;
    float* b1s   = sm + 21560;
    float* b2s   = sm + 21576;
    float* red   = sm + 21608;

    const int tid = threadIdx.x;
    const int b   = blockIdx.x;

    // ---- weights into smem ----
    for (int t = tid; t < W2R_ELEMS; t += 256) W2Rs[t] = w2r[t];
    if (tid < 240) w1s[tid] = w1[tid];
    if (tid < 16) b1s[tid] = b1[tid];
    if (tid < 32) b2s[tid] = b2[tid];

    // ---- gather the two e rows into padded xp[2][516] ----
    int id = idx[b];
    int r_no = id / NP, p_no = id % NP;
    const float* rrow = eAll + (size_t)r_no * DCOL;
    const float* prow = eAll + (size_t)(NR + p_no) * DCOL;
    for (int t = tid; t < 1024; t += 256) {
        int rr = t >> 9, c = t & 511;
        xp[rr * 516 + 2 + c] = rr ? prow[c] : rrow[c];
    }
    if (tid < 8) {
        int rr = tid >> 2, q = tid & 3;
        xp[rr * 516 + (q < 2 ? q : 512 + q)] = 0.0f;
    }
    // zero W-pads of XPh: pc in {0,1,258,259}, ih in {0,1}, c in 0..15
    if (tid < 128) {
        int c = tid & 15, rest = tid >> 4;       // rest 0..7
        int ih = rest >> 2, pcidx = rest & 3;
        int pc = (pcidx < 2) ? pcidx : 256 + pcidx;
        XPh[ih * 4160 + pc * 16 + c] = __float2half_rn(0.0f);
    }
    __syncthreads();

    // ---- conv1 (16ch, 3x5, pad 2) + leaky + avgpool2 -> XPh[ih][2+pw][c] fp16 ----
    // iteration i: ph = i&1, c = i>>1 (warp-uniform), pw = tid.
    // The 2x2 pooling cell reads 12 unique inputs (2 rows x 6 cols), loaded
    // as 6 float2 (even-aligned, lane-stride 8B -> conflict-free). Weights
    // hoisted per channel (reload every 2nd iteration). FMA order unchanged.
    {
        float wreg[15];
        float bc = 0.0f;
#pragma unroll 2
        for (int i = 0; i < 32; ++i) {
            const int ph = i & 1, c = i >> 1;
            if ((i & 1) == 0) {
                bc = b1s[c];
#pragma unroll
                for (int t = 0; t < 15; ++t) wreg[t] = w1s[c * 15 + t];
            }
            const int ow0 = 2 * tid;
            const float2* x0 = (const float2*)(xp + ow0);
            const float2* x1 = (const float2*)(xp + 516 + ow0);
            float2 a0[3], a1[3];
#pragma unroll
            for (int t = 0; t < 3; ++t) { a0[t] = x0[t]; a1[t] = x1[t]; }
            float r0[6] = {a0[0].x, a0[0].y, a0[1].x, a0[1].y, a0[2].x, a0[2].y};
            float r1[6] = {a1[0].x, a1[0].y, a1[1].x, a1[1].y, a1[2].x, a1[2].y};

            float sum = 0.0f;
#pragma unroll
            for (int dr = 0; dr < 2; ++dr) {
                int oh = 2 * ph + dr;
#pragma unroll
                for (int dc = 0; dc < 2; ++dc) {
                    float v = bc;
                    int kh = 2 - oh;
                    if (kh >= 0) {
#pragma unroll
                        for (int kw = 0; kw < 5; ++kw)
                            v = fmaf(r0[dc + kw], wreg[kh * 5 + kw], v);
                    }
                    kh = 3 - oh;
                    if (kh < 3) {
#pragma unroll
                        for (int kw = 0; kw < 5; ++kw)
                            v = fmaf(r1[dc + kw], wreg[kh * 5 + kw], v);
                    }
                    sum += lrelu(v);
                }
            }
            XPh[ph * 4160 + (2 + tid) * 16 + c] = __float2half_rn(0.25f * sum);
        }
    }
    __syncthreads();

    // ---- conv2 via wmma implicit GEMM + bias + leaky + maxpool2 + tanh ----
    {
        const int w    = tid >> 5;
        const int lane = tid & 31;
        const int ph2   = w & 1;
        const int ntile = (w >> 1) & 1;
        const int mhalf = w >> 2;
        float* S = sS + w * 512;       // [2][16][16]

        const int khA = ph2 ? 0 : 1;   // lower kh of this pair
        wmma::fragment<wmma::matrix_b, 16, 16, 16, __half, wmma::row_major> bA[5], bB[5];
#pragma unroll
        for (int kw = 0; kw < 5; ++kw) {
            wmma::load_matrix_sync(bA[kw],
                W2Rs + ((khA * 5 + kw) * 16) * 32 + ntile * 16, 32);
            wmma::load_matrix_sync(bB[kw],
                W2Rs + (((khA + 1) * 5 + kw) * 16) * 32 + ntile * 16, 32);
        }

#pragma unroll 1
        for (int j = 0; j < 8; ++j) {
            const int mt = mhalf * 8 + j;          // m-tile: ow base mt*16
            wmma::fragment<wmma::accumulator, 16, 16, 16, float> acc0, acc1;
            wmma::fill_fragment(acc0, 0.0f);
            wmma::fill_fragment(acc1, 0.0f);

#pragma unroll
            for (int kw = 0; kw < 5; ++kw) {
                wmma::fragment<wmma::matrix_a, 16, 16, 16, __half, wmma::row_major> a;
                const __half* base = XPh + (mt * 16 + kw) * 16;
                if (ph2 == 0) {
                    wmma::load_matrix_sync(a, base, 16);              // ih0
                    wmma::mma_sync(acc0, a, bB[kw], acc0);
                    wmma::mma_sync(acc1, a, bA[kw], acc1);
                    wmma::load_matrix_sync(a, base + 4160, 16);       // ih1
                    wmma::mma_sync(acc1, a, bB[kw], acc1);
                } else {
                    wmma::load_matrix_sync(a, base, 16);              // ih0
                    wmma::mma_sync(acc0, a, bA[kw], acc0);
                    wmma::load_matrix_sync(a, base + 4160, 16);       // ih1
                    wmma::mma_sync(acc0, a, bB[kw], acc0);
                    wmma::mma_sync(acc1, a, bA[kw], acc1);
                }
            }

            wmma::store_matrix_sync(S,       acc0, 16, wmma::mem_row_major);
            wmma::store_matrix_sync(S + 256, acc1, 16, wmma::mem_row_major);
            __syncwarp();

#pragma unroll
            for (int q = 0; q < 4; ++q) {
                int p = q * 32 + lane;           // 0..127
                int n = p & 15, w2c = p >> 4;    // oc-local, pooled col 0..7
                float bias = b2s[ntile * 16 + n];
                int m0i = 2 * w2c * 16 + n;
                float v00 = lrelu(S[m0i] + bias);
                float v01 = lrelu(S[m0i + 16] + bias);
                float v10 = lrelu(S[256 + m0i] + bias);
                float v11 = lrelu(S[256 + m0i + 16] + bias);
                float m = fmaxf(fmaxf(v00, v01), fmaxf(v10, v11));
                flatS[(ntile * 16 + n) * 256 + ph2 * 128 + mt * 8 + w2c] = tanh_fast(m);
            }
            __syncwarp();
        }
    }
    __syncthreads();

    // ---- coalesced flat store ----
    float4* fdst = (float4*)(flatG + (size_t)b * 8192);
    const float4* fsrc = (const float4*)flatS;
#pragma unroll
    for (int q = 0; q < 8; ++q) fdst[tid + q * 256] = fsrc[tid + q * 256];

    // ---- head: out = flat @ W_out + b_out ----
    float p0 = 0.0f, p1 = 0.0f;
    for (int j = tid; j < 8192; j += 256) {
        float f = flatS[j];
        p0 = fmaf(f, Wout[2 * j], p0);
        p1 = fmaf(f, Wout[2 * j + 1], p1);
    }
#pragma unroll
    for (int off = 16; off; off >>= 1) {
        p0 += __shfl_down_sync(0xffffffffu, p0, off);
        p1 += __shfl_down_sync(0xffffffffu, p1, off);
    }
    if ((tid & 31) == 0) { red[2 * (tid >> 5)] = p0; red[2 * (tid >> 5) + 1] = p1; }
    __syncthreads();
    if (tid == 0) {
        float s0 = bout[0], s1 = bout[1];
#pragma unroll
        for (int wq = 0; wq < 8; ++wq) { s0 += red[2 * wq]; s1 += red[2 * wq + 1]; }
        outG[(size_t)b * 2]     = s0;
        outG[(size_t)b * 2 + 1] = s1;
    }
}

// ---------------- launch ----------------
extern "C" void kernel_launch(void* const* d_in, const int* in_sizes, int n_in,
                              void* d_out, int out_size)
{
    const float* r_att  = (const float*)d_in[0];
    const float* p_att  = (const float*)d_in[1];
    const float* r_fun  = (const float*)d_in[2];
    const float* p_fun  = (const float*)d_in[3];
    const int*   idx    = (const int*)d_in[4];
    const float* W_att1 = (const float*)d_in[5];
    const float* b_att1 = (const float*)d_in[6];
    const float* W_att2 = (const float*)d_in[7];
    const float* b_att2 = (const float*)d_in[8];
    const float* W_fun1 = (const float*)d_in[9];
    const float* b_fun1 = (const float*)d_in[10];
    const float* W_fun2 = (const float*)d_in[11];
    const float* b_fun2 = (const float*)d_in[12];
    const float* c1w    = (const float*)d_in[13];
    const float* c1b    = (const float*)d_in[14];
    const float* c2w    = (const float*)d_in[15];
    const float* c2b    = (const float*)d_in[16];
    const float* Wout   = (const float*)d_in[17];
    const float* bout   = (const float*)d_in[18];
    float* out = (float*)d_out;

    __half *H1, *H2, *AA, *AF, *WT1, *WT2, *WT3, *WT4, *W2R;
    cudaGetSymbolAddress((void**)&H1,  g_H1);
    cudaGetSymbolAddress((void**)&H2,  g_H2);
    cudaGetSymbolAddress((void**)&AA,  g_AA);
    cudaGetSymbolAddress((void**)&AF,  g_AF);
    cudaGetSymbolAddress((void**)&WT1, g_WT1);
    cudaGetSymbolAddress((void**)&WT2, g_WT2);
    cudaGetSymbolAddress((void**)&WT3, g_WT3);
    cudaGetSymbolAddress((void**)&WT4, g_WT4);
    cudaGetSymbolAddress((void**)&W2R, g_W2R);

    // prep: float -> half (FUN rows padded), conv2 weight reorg
    pad_copy_h<<<NR, 256>>>(r_att, AA, KATT, KATT);
    pad_copy_h<<<NP, 256>>>(p_att, AA + (size_t)NR * KATT, KATT, KATT);
    pad_copy_h<<<NR, 256>>>(r_fun, AF, KFUN, KFUN_PAD);
    pad_copy_h<<<NP, 256>>>(p_fun, AF + (size_t)NR * KFUN_PAD, KFUN, KFUN_PAD);
    reorg_w2<<<(W2R_ELEMS + 255) / 256, 256>>>(c2w, W2R);

    dim3 tb(32, 8);
    transpose_h<<<dim3(94, 64),   tb>>>(W_att1, WT1, KATT, 2048, KATT);
    transpose_h<<<dim3(176, 128), tb>>>(W_fun1, WT2, KFUN, 4096, KFUN_PAD);
    transpose_h<<<dim3(64, 8),    tb>>>(W_att2, WT3, 2048, 256, 2048);
    transpose_h<<<dim3(128, 8),   tb>>>(W_fun2, WT4, 4096, 256, 4096);

    cudaFuncSetAttribute(gemm_h<0>, cudaFuncAttributeMaxDynamicSharedMemorySize, GEMM_SMEM);
    cudaFuncSetAttribute(gemm_h<1>, cudaFuncAttributeMaxDynamicSharedMemorySize, GEMM_SMEM);

    // layer 1 (gelu -> half H)
    gemm_h<0><<<dim3(28, 8), 256, GEMM_SMEM>>>(AA, WT1, b_att1,
                                               H1, MROWS, KATT, KATT, KATT, 2048, 0);
    gemm_h<0><<<dim3(28, 16), 256, GEMM_SMEM>>>(AF, WT2, b_fun1,
                                                H2, MROWS, KFUN, KFUN_PAD, KFUN_PAD, 4096, 0);
    // layer 2 (sigmoid -> float) directly into d_out's e region
    gemm_h<1><<<dim3(28, 1), 256, GEMM_SMEM>>>(H1, WT3, b_att2,
                                               out, MROWS, 2048, 2048, 2048, DCOL, 0);
    gemm_h<1><<<dim3(28, 1), 256, GEMM_SMEM>>>(H2, WT4, b_fun2,
                                               out, MROWS, 4096, 4096, 4096, DCOL, 256);

    cudaFuncSetAttribute(conv_fused, cudaFuncAttributeMaxDynamicSharedMemorySize,
                         CONV_SMEM_FLOATS * 4);
    conv_fused<<<BBATCH, 256, CONV_SMEM_FLOATS * 4>>>(out, idx, c1w, c1b, W2R, c2b,
                                                      Wout, bout,
                                                      out + OUT_OFF, out + FLAT_OFF);
}